// round 4
// baseline (speedup 1.0000x reference)
#include <cuda_runtime.h>
#include <cstdint>

// Problem constants (match reference_code)
#define IMG_W 3840
#define IMG_H 2160
#define NPIX (IMG_W * IMG_H)

#define SCALE_F 0.001f
#define D_CX 1919.5f
#define D_CY 1079.5f
#define D_FX 3000.0f
#define D_FY 3000.0f
#define R_CX 1919.5f
#define R_CY 1079.5f
#define R_FX 3050.0f
#define R_FY 3050.0f
#define FILL 10000.0f

// ---------------------------------------------------------------------------
// Kernel 1: initialize output to FILL (vectorized, NPIX % 4 == 0)
// ---------------------------------------------------------------------------
__global__ void init_fill_kernel(float4* __restrict__ out4) {
    int i = blockIdx.x * blockDim.x + threadIdx.x;
    if (i < NPIX / 4) {
        out4[i] = make_float4(FILL, FILL, FILL, FILL);
    }
}

// ---------------------------------------------------------------------------
// Kernel 2: project each depth pixel and min-splat raw depth into 2x2 window.
//
// Rounding model (current best hypothesis of the reference lowering):
//   - grid: (u-cx) * rn(1/fx) * SCALE   <-- XLA div-by-constant -> mul-by-
//     reciprocal rewrite (THE change this round); each op rn, no contraction.
//   - pts = depth*grid: rn muls.
//   - dot: rounded mul + left-assoc rounded adds, NO fma (R3, best so far).
//   - translation add, projection div/mul/add: separate rn ops.
//   - trunc-toward-zero int casts.
//
// Output treated as int bits: all candidate values are non-negative floats,
// so integer ordering of bit patterns == float ordering -> atomicMin on int.
// Check-before-atomic via __ldcg kills same-address serialization (masked
// pixels all target (0,0)).
// ---------------------------------------------------------------------------
__global__ void splat_kernel(const float* __restrict__ depth,
                             const float* __restrict__ Rm,   // 9 floats, row-major
                             const float* __restrict__ Tv,   // 3 floats
                             int* __restrict__ outbits) {
    int u = blockIdx.x * blockDim.x + threadIdx.x;
    int v = blockIdx.y;
    if (u >= IMG_W) return;
    int idx = v * IMG_W + u;

    float dval = depth[idx];

    // Reciprocals of the constant focal lengths, rounded-to-nearest once
    // (compile-time fold of 1.0f/3000.0f is rn -> identical to __fdiv_rn).
    const float INV_DFX = 1.0f / D_FX;
    const float INV_DFY = 1.0f / D_FY;

    // grid = stack((u-cx)*(1/fx), (v-cy)*(1/fy), 1) * SCALE  -- separate rn ops
    float gx = __fmul_rn(__fmul_rn(__fsub_rn((float)u, D_CX), INV_DFX), SCALE_F);
    float gy = __fmul_rn(__fmul_rn(__fsub_rn((float)v, D_CY), INV_DFY), SCALE_F);
    float gz = SCALE_F;  // 1.0f * SCALE

    // pts = depth * grid  -- separate rn muls
    float p0 = __fmul_rn(dval, gx);
    float p1 = __fmul_rn(dval, gy);
    float p2 = __fmul_rn(dval, gz);

    // Broadcast loads (uniform across warp)
    float r00 = Rm[0], r01 = Rm[1], r02 = Rm[2];
    float r10 = Rm[3], r11 = Rm[4], r12 = Rm[5];
    float r20 = Rm[6], r21 = Rm[7], r22 = Rm[8];
    float t0 = Tv[0], t1 = Tv[1], t2 = Tv[2];

    // pts @ R : multiply-reduce, separate rn ops, left-assoc, NO fma.
    float x = __fadd_rn(__fadd_rn(__fmul_rn(p0, r00), __fmul_rn(p1, r10)),
                        __fmul_rn(p2, r20));
    float y = __fadd_rn(__fadd_rn(__fmul_rn(p0, r01), __fmul_rn(p1, r11)),
                        __fmul_rn(p2, r21));
    float d = __fadd_rn(__fadd_rn(__fmul_rn(p0, r02), __fmul_rn(p1, r12)),
                        __fmul_rn(p2, r22));

    // + translation (separate rn add)
    x = __fadd_rn(x, t0);
    y = __fadd_rn(y, t1);
    d = __fadd_rn(d, t2);

    // projection: div, mul, add as SEPARATE rn ops (no fma)
    float dsafe = (d == 0.0f) ? 1.0f : d;
    float px = __fadd_rn(__fmul_rn(__fdiv_rn(x, dsafe), R_FX), R_CX);
    float py = __fadd_rn(__fmul_rn(__fdiv_rn(y, dsafe), R_FY), R_CY);
    if (d == 0.0f) { px = 0.0f; py = 0.0f; }

    // bounds mask -> redirect to (0,0) like the reference
    bool mask = (px < 0.0f) | (px >= (float)IMG_W) | (py < 0.0f) | (py >= (float)IMG_H);
    if (mask) { px = 0.0f; py = 0.0f; }

    // trunc-toward-zero (astype(int32)); px-0.5 / px+0.5 are exact-rounded rn
    int px0 = (int)__fsub_rn(px, 0.5f);
    int px1 = (int)__fadd_rn(px, 0.5f);
    int py0 = (int)__fsub_rn(py, 0.5f);
    int py1 = (int)__fadd_rn(py, 0.5f);

    int vb = __float_as_int(dval);

    // splat with bounds drop (jax drops OOB scatter indices, e.g. px1 == W)
    #define SPLAT(yy, xx)                                                     \
        do {                                                                  \
            if ((unsigned)(xx) < IMG_W && (unsigned)(yy) < IMG_H) {           \
                int o = (yy) * IMG_W + (xx);                                  \
                if (__ldcg(&outbits[o]) > vb) atomicMin(&outbits[o], vb);     \
            }                                                                 \
        } while (0)

    bool xdup = (px1 == px0);
    bool ydup = (py1 == py0);
    SPLAT(py0, px0);
    if (!xdup) SPLAT(py0, px1);
    if (!ydup) {
        SPLAT(py1, px0);
        if (!xdup) SPLAT(py1, px1);
    }
    #undef SPLAT
}

// ---------------------------------------------------------------------------
// Kernel 3: FILL -> 0 (vectorized)
// ---------------------------------------------------------------------------
__global__ void finalize_kernel(float4* __restrict__ out4) {
    int i = blockIdx.x * blockDim.x + threadIdx.x;
    if (i < NPIX / 4) {
        float4 q = out4[i];
        q.x = (q.x == FILL) ? 0.0f : q.x;
        q.y = (q.y == FILL) ? 0.0f : q.y;
        q.z = (q.z == FILL) ? 0.0f : q.z;
        q.w = (q.w == FILL) ? 0.0f : q.w;
        out4[i] = q;
    }
}

extern "C" void kernel_launch(void* const* d_in, const int* in_sizes, int n_in,
                              void* d_out, int out_size) {
    const float* depth = (const float*)d_in[0];   // [H, W, 1] float32
    const float* Rm    = (const float*)d_in[1];   // [3, 3]
    const float* Tv    = (const float*)d_in[2];   // [3]
    float* out = (float*)d_out;                   // [H, W, 1] float32

    (void)in_sizes; (void)n_in; (void)out_size;

    {
        int n4 = NPIX / 4;
        int threads = 256;
        int blocks = (n4 + threads - 1) / threads;
        init_fill_kernel<<<blocks, threads>>>((float4*)out);
    }
    {
        dim3 threads(256, 1, 1);
        dim3 blocks(IMG_W / 256, IMG_H, 1);  // 3840 = 15 * 256
        splat_kernel<<<blocks, threads>>>(depth, Rm, Tv, (int*)out);
    }
    {
        int n4 = NPIX / 4;
        int threads = 256;
        int blocks = (n4 + threads - 1) / threads;
        finalize_kernel<<<blocks, threads>>>((float4*)out);
    }
}

// round 5
// speedup vs baseline: 1.9306x; 1.9306x over previous
#include <cuda_runtime.h>
#include <cstdint>

// Problem constants (match reference_code)
#define IMG_W 3840
#define IMG_H 2160
#define NPIX (IMG_W * IMG_H)

#define SCALE_F 0.001f
#define D_CX 1919.5f
#define D_CY 1079.5f
#define D_FX 3000.0f
#define D_FY 3000.0f
#define R_CX 1919.5f
#define R_CY 1079.5f
#define R_FX 3050.0f
#define R_FY 3050.0f
#define FILL 10000.0f

// ---------------------------------------------------------------------------
// Kernel 1: initialize output to FILL (vectorized, NPIX % 4 == 0)
// ---------------------------------------------------------------------------
__global__ void init_fill_kernel(float4* __restrict__ out4) {
    int i = blockIdx.x * blockDim.x + threadIdx.x;
    if (i < NPIX / 4) {
        out4[i] = make_float4(FILL, FILL, FILL, FILL);
    }
}

// ---------------------------------------------------------------------------
// Kernel 2: project + min-splat. 4 source pixels per thread (float4 load).
//
// Numerics: FROZEN from round 4 (bit-exact vs reference):
//   grid = (u-cx)*rn(1/fx)*SCALE   (XLA const-div->mul rewrite)
//   dot  = rounded mul + left-assoc rounded adds, no fma
//   proj = separate rn div/mul/add
//   trunc-toward-zero int casts
//
// Splat policy:
//   - in-bounds targets: unconditional atomicMin (REDG fire-and-forget;
//     addresses are well spread -> no serialization)
//   - masked pixels (all 4 targets collapse to (0,0)): __ldcg check-before-
//     atomic to kill same-address serialization after warm-up
// ---------------------------------------------------------------------------
__global__ void splat_kernel(const float4* __restrict__ depth4,
                             const float* __restrict__ Rm,   // 9 floats
                             const float* __restrict__ Tv,   // 3 floats
                             int* __restrict__ outbits) {
    int i4 = blockIdx.x * blockDim.x + threadIdx.x;
    if (i4 >= NPIX / 4) return;

    const int W4 = IMG_W / 4;             // 960
    int v  = i4 / W4;
    int u0 = (i4 - v * W4) * 4;

    float4 dq = depth4[i4];
    float dvals[4] = {dq.x, dq.y, dq.z, dq.w};

    // Broadcast loads (uniform across warp)
    float r00 = Rm[0], r01 = Rm[1], r02 = Rm[2];
    float r10 = Rm[3], r11 = Rm[4], r12 = Rm[5];
    float r20 = Rm[6], r21 = Rm[7], r22 = Rm[8];
    float t0 = Tv[0], t1 = Tv[1], t2 = Tv[2];

    const float INV_DFX = 1.0f / D_FX;
    const float INV_DFY = 1.0f / D_FY;

    // gy depends only on v: hoist
    float gy = __fmul_rn(__fmul_rn(__fsub_rn((float)v, D_CY), INV_DFY), SCALE_F);

    #pragma unroll
    for (int j = 0; j < 4; j++) {
        int u = u0 + j;
        float dval = dvals[j];

        float gx = __fmul_rn(__fmul_rn(__fsub_rn((float)u, D_CX), INV_DFX), SCALE_F);
        float gz = SCALE_F;

        float p0 = __fmul_rn(dval, gx);
        float p1 = __fmul_rn(dval, gy);
        float p2 = __fmul_rn(dval, gz);

        // pts @ R : multiply-reduce, separate rn ops, left-assoc, NO fma.
        float x = __fadd_rn(__fadd_rn(__fmul_rn(p0, r00), __fmul_rn(p1, r10)),
                            __fmul_rn(p2, r20));
        float y = __fadd_rn(__fadd_rn(__fmul_rn(p0, r01), __fmul_rn(p1, r11)),
                            __fmul_rn(p2, r21));
        float d = __fadd_rn(__fadd_rn(__fmul_rn(p0, r02), __fmul_rn(p1, r12)),
                            __fmul_rn(p2, r22));

        x = __fadd_rn(x, t0);
        y = __fadd_rn(y, t1);
        d = __fadd_rn(d, t2);

        float dsafe = (d == 0.0f) ? 1.0f : d;
        float px = __fadd_rn(__fmul_rn(__fdiv_rn(x, dsafe), R_FX), R_CX);
        float py = __fadd_rn(__fmul_rn(__fdiv_rn(y, dsafe), R_FY), R_CY);
        if (d == 0.0f) { px = 0.0f; py = 0.0f; }

        bool mask = (px < 0.0f) | (px >= (float)IMG_W) |
                    (py < 0.0f) | (py >= (float)IMG_H);

        int vb = __float_as_int(dval);

        if (mask) {
            // all four targets collapse to (0,0): guarded single atomic
            if (__ldcg(&outbits[0]) > vb) atomicMin(&outbits[0], vb);
            continue;
        }

        // trunc-toward-zero (astype(int32))
        int px0 = (int)__fsub_rn(px, 0.5f);
        int px1 = (int)__fadd_rn(px, 0.5f);
        int py0 = (int)__fsub_rn(py, 0.5f);
        int py1 = (int)__fadd_rn(py, 0.5f);

        // px0,py0 >= 0 guaranteed (px,py >= 0); px1/py1 may hit W/H (dropped)
        bool x1ok = (px1 < IMG_W) & (px1 != px0);
        bool y1ok = (py1 < IMG_H) & (py1 != py0);

        int o00 = py0 * IMG_W + px0;
        atomicMin(&outbits[o00], vb);
        if (x1ok) atomicMin(&outbits[o00 + 1], vb);
        if (y1ok) {
            int o10 = py1 * IMG_W + px0;
            atomicMin(&outbits[o10], vb);
            if (x1ok) atomicMin(&outbits[o10 + 1], vb);
        }
    }
}

// ---------------------------------------------------------------------------
// Kernel 3: FILL -> 0 (vectorized)
// ---------------------------------------------------------------------------
__global__ void finalize_kernel(float4* __restrict__ out4) {
    int i = blockIdx.x * blockDim.x + threadIdx.x;
    if (i < NPIX / 4) {
        float4 q = out4[i];
        q.x = (q.x == FILL) ? 0.0f : q.x;
        q.y = (q.y == FILL) ? 0.0f : q.y;
        q.z = (q.z == FILL) ? 0.0f : q.z;
        q.w = (q.w == FILL) ? 0.0f : q.w;
        out4[i] = q;
    }
}

extern "C" void kernel_launch(void* const* d_in, const int* in_sizes, int n_in,
                              void* d_out, int out_size) {
    const float* depth = (const float*)d_in[0];   // [H, W, 1] float32
    const float* Rm    = (const float*)d_in[1];   // [3, 3]
    const float* Tv    = (const float*)d_in[2];   // [3]
    float* out = (float*)d_out;                   // [H, W, 1] float32

    (void)in_sizes; (void)n_in; (void)out_size;

    int n4 = NPIX / 4;
    int threads = 256;
    int blocks4 = (n4 + threads - 1) / threads;

    init_fill_kernel<<<blocks4, threads>>>((float4*)out);
    splat_kernel<<<blocks4, threads>>>((const float4*)depth, Rm, Tv, (int*)out);
    finalize_kernel<<<blocks4, threads>>>((float4*)out);
}